// round 5
// baseline (speedup 1.0000x reference)
#include <cuda_runtime.h>
#include <cstdint>

// ---------------- problem constants ----------------
#define N0 200000
#define N1 50000
#define N2 12500
#define E0 6400000
#define E1 1600000
#define E2 400000
#define KC0 24      // 6 cheb orders * 4 (padded cin=3 -> 4)
#define KC1 384     // 6 * 64
#define KC2 768     // 6 * 128
#define LINLEN 3200000  // 12500 * 256

// ---------------- static scratch (no allocation allowed) ----------------
__device__ int    g_deg[N0];
__device__ float  g_dinv[N0];
__device__ int    g_rstart[N0];
__device__ int    g_cursor[N0];
__device__ int    g_bsum[256];
__device__ float2 g_csr[E0];                       // (col-as-bits, norm) reused per level
__device__ float  g_T0[(size_t)N0 * KC0];
__device__ float  g_h0[(size_t)N0 * 64];
__device__ float  g_T1[(size_t)N1 * KC1];
__device__ float  g_h1[(size_t)N1 * 128];
__device__ float  g_T2[(size_t)N2 * KC2];
__device__ float  g_h2[(size_t)N2 * 256];

static inline int cdiv(int a, int b) { return (a + b - 1) / b; }

// ---------------- graph build ----------------
__global__ void k_zero_i(int* p, int n) {
    int i = blockIdx.x * blockDim.x + threadIdx.x;
    if (i < n) p[i] = 0;
}

__global__ void k_hist(const int* __restrict__ ei, int E, int* __restrict__ deg) {
    int e = blockIdx.x * blockDim.x + threadIdx.x;
    if (e < E) {
        int r = ei[e], c = ei[E + e];
        if (r != c) atomicAdd(&deg[r], 1);
    }
}

__global__ void k_dinv(const int* __restrict__ deg, float* __restrict__ dinv, int n) {
    int i = blockIdx.x * blockDim.x + threadIdx.x;
    if (i < n) {
        int d = deg[i];
        dinv[i] = d > 0 ? rsqrtf((float)d) : 0.f;
    }
}

// scan: 4096 elems per block
__global__ void k_scan_reduce(const int* __restrict__ deg, int n, int* __restrict__ bsum) {
    __shared__ int sm[1024];
    int base = blockIdx.x * 4096;
    int s = 0;
    for (int i = threadIdx.x; i < 4096; i += 1024) {
        int id = base + i;
        if (id < n) s += deg[id];
    }
    sm[threadIdx.x] = s;
    __syncthreads();
    for (int o = 512; o > 0; o >>= 1) {
        if (threadIdx.x < o) sm[threadIdx.x] += sm[threadIdx.x + o];
        __syncthreads();
    }
    if (threadIdx.x == 0) bsum[blockIdx.x] = sm[0];
}

__global__ void k_scan_bsum(int* bsum, int nb) {
    if (threadIdx.x == 0) {
        int acc = 0;
        for (int i = 0; i < nb; i++) { int v = bsum[i]; bsum[i] = acc; acc += v; }
    }
}

__global__ void k_scan_write(const int* __restrict__ deg, int n, const int* __restrict__ bsum,
                             int* __restrict__ rstart, int* __restrict__ cursor) {
    __shared__ int wsum[32];
    int lane = threadIdx.x & 31, wid = threadIdx.x >> 5;
    int base = blockIdx.x * 4096;
    int idx0 = base + threadIdx.x * 4;
    int v[4]; int s = 0;
#pragma unroll
    for (int j = 0; j < 4; j++) {
        int id = idx0 + j;
        v[j] = (id < n) ? deg[id] : 0;
        s += v[j];
    }
    int x = s;
#pragma unroll
    for (int o = 1; o < 32; o <<= 1) {
        int y = __shfl_up_sync(0xffffffffu, x, o);
        if (lane >= o) x += y;
    }
    if (lane == 31) wsum[wid] = x;
    __syncthreads();
    if (wid == 0) {
        int w = wsum[lane];
#pragma unroll
        for (int o = 1; o < 32; o <<= 1) {
            int y = __shfl_up_sync(0xffffffffu, w, o);
            if (lane >= o) w += y;
        }
        wsum[lane] = w;
    }
    __syncthreads();
    int run = bsum[blockIdx.x] + (wid ? wsum[wid - 1] : 0) + (x - s);
#pragma unroll
    for (int j = 0; j < 4; j++) {
        int id = idx0 + j;
        if (id < n) { rstart[id] = run; cursor[id] = run; }
        run += v[j];
    }
}

__global__ void k_fill(const int* __restrict__ ei, int E, const float* __restrict__ dinv,
                       int* __restrict__ cursor, float2* __restrict__ csr) {
    int e = blockIdx.x * blockDim.x + threadIdx.x;
    if (e < E) {
        int r = ei[e], c = ei[E + e];
        if (r != c) {
            int p = atomicAdd(&cursor[r], 1);
            csr[p] = make_float2(__int_as_float(c), -dinv[r] * dinv[c]);
        }
    }
}

// ---------------- level 0 ----------------
__global__ void k_pad_x(const float* __restrict__ x, float* __restrict__ T0, int n) {
    int i = blockIdx.x * blockDim.x + threadIdx.x;
    if (i < n) {
        float4 v;
        v.x = x[3 * i]; v.y = x[3 * i + 1]; v.z = x[3 * i + 2]; v.w = 0.f;
        *reinterpret_cast<float4*>(T0 + (size_t)i * KC0) = v;
    }
}

// width-4 propagation: warp per node, lanes over edges, float4 gather + warp reduce
template <bool HASPP>
__global__ void k_prop_w4(const float2* __restrict__ csr, const int* __restrict__ rstart,
                          const int* __restrict__ deg, float* __restrict__ T,
                          int off_src, int off_dst, int off_pp, int n) {
    int warp = (blockIdx.x * blockDim.x + threadIdx.x) >> 5;
    if (warp >= n) return;
    int lane = threadIdx.x & 31;
    int s = rstart[warp], d = deg[warp];
    const float* src = T + off_src;
    float ax = 0.f, ay = 0.f, az = 0.f, aw = 0.f;
    for (int e = s + lane; e < s + d; e += 32) {
        float2 cw = csr[e];
        int c = __float_as_int(cw.x);
        float w = cw.y;
        float4 h = *reinterpret_cast<const float4*>(src + (size_t)c * KC0);
        ax += w * h.x; ay += w * h.y; az += w * h.z; aw += w * h.w;
    }
#pragma unroll
    for (int o = 16; o; o >>= 1) {
        ax += __shfl_xor_sync(0xffffffffu, ax, o);
        ay += __shfl_xor_sync(0xffffffffu, ay, o);
        az += __shfl_xor_sync(0xffffffffu, az, o);
        aw += __shfl_xor_sync(0xffffffffu, aw, o);
    }
    if (lane == 0) {
        float4 r = make_float4(ax, ay, az, aw);
        if (HASPP) {
            float4 p = *reinterpret_cast<const float4*>(T + off_pp + (size_t)warp * KC0);
            r.x = 2.f * ax - p.x; r.y = 2.f * ay - p.y; r.z = 2.f * az - p.z; r.w = 2.f * aw - p.w;
        }
        *reinterpret_cast<float4*>(T + off_dst + (size_t)warp * KC0) = r;
    }
}

// wide propagation: warp per node, lanes over channels, broadcast edge loads
template <int CIN, int KC, bool HASPP>
__global__ void k_prop_wide(const float2* __restrict__ csr, const int* __restrict__ rstart,
                            const int* __restrict__ deg, float* __restrict__ T,
                            int off_src, int off_dst, int off_pp, int n) {
    int warp = (blockIdx.x * blockDim.x + threadIdx.x) >> 5;
    if (warp >= n) return;
    int lane = threadIdx.x & 31;
    int s = rstart[warp], d = deg[warp];
    constexpr int R = CIN / 32;
    float acc[R];
#pragma unroll
    for (int i = 0; i < R; i++) acc[i] = 0.f;
    const float* src = T + off_src;
    int e = s, end = s + d;
    for (; e + 1 < end; e += 2) {
        float2 cw0 = __ldg(&csr[e]);
        float2 cw1 = __ldg(&csr[e + 1]);
        int c0 = __float_as_int(cw0.x); float w0 = cw0.y;
        int c1 = __float_as_int(cw1.x); float w1 = cw1.y;
        const float* h0 = src + (size_t)c0 * KC + lane;
        const float* h1 = src + (size_t)c1 * KC + lane;
#pragma unroll
        for (int i = 0; i < R; i++) acc[i] += w0 * h0[32 * i];
#pragma unroll
        for (int i = 0; i < R; i++) acc[i] += w1 * h1[32 * i];
    }
    if (e < end) {
        float2 cw = __ldg(&csr[e]);
        int c = __float_as_int(cw.x); float w = cw.y;
        const float* h = src + (size_t)c * KC + lane;
#pragma unroll
        for (int i = 0; i < R; i++) acc[i] += w * h[32 * i];
    }
    float* dst = T + off_dst + (size_t)warp * KC + lane;
    if (HASPP) {
        const float* pp = T + off_pp + (size_t)warp * KC + lane;
#pragma unroll
        for (int i = 0; i < R; i++) dst[32 * i] = 2.f * acc[i] - pp[32 * i];
    } else {
#pragma unroll
        for (int i = 0; i < R; i++) dst[32 * i] = acc[i];
    }
}

// ---------------- level-0 GEMM: [n,24(pad)] x w0[6,3,64] + relu ----------------
__global__ void k_gemm0(const float* __restrict__ T0, const float* __restrict__ w,
                        const float* __restrict__ b, float* __restrict__ h0, int n) {
    __shared__ float Ws[1152];   // 6*3*64
    __shared__ float As[16][24];
    int tid = threadIdx.x;
    for (int i = tid; i < 1152; i += 256) Ws[i] = w[i];
    int node0 = blockIdx.x * 16;
    for (int i = tid; i < 384; i += 256) {
        int nn = i / 24, j = i % 24;
        int nd = node0 + nn;
        As[nn][j] = (nd < n) ? T0[(size_t)nd * KC0 + j] : 0.f;
    }
    __syncthreads();
    int co = tid & 63, g = tid >> 6;  // g in 0..3
#pragma unroll
    for (int sblk = 0; sblk < 4; sblk++) {
        int nn = g * 4 + sblk;
        int node = node0 + nn;
        if (node < n) {
            float s = b[co];
#pragma unroll
            for (int k = 0; k < 6; k++)
#pragma unroll
                for (int j = 0; j < 3; j++)
                    s += As[nn][k * 4 + j] * Ws[(k * 3 + j) * 64 + co];
            h0[(size_t)node * 64 + co] = fmaxf(s, 0.f);
        }
    }
}

// ---------------- SGEMM 128x128x8, 256 threads, 8x8 per thread ----------------
__global__ __launch_bounds__(256) void k_sgemm(const float* __restrict__ A, const float* __restrict__ B,
                                               float* __restrict__ C, int M, int N, int K,
                                               const float* __restrict__ bias, int relu) {
    __shared__ float As[8][128];
    __shared__ float Bs[8][128];
    int tid = threadIdx.x;
    int tx = tid & 15, ty = tid >> 4;
    int rowBase = blockIdx.y * 128;
    int colBase = blockIdx.x * 128;
    float acc[8][8];
#pragma unroll
    for (int i = 0; i < 8; i++)
#pragma unroll
        for (int j = 0; j < 8; j++) acc[i][j] = 0.f;

    int aRow = tid >> 1;
    int aCol = (tid & 1) * 4;
    int bRow = tid >> 5;
    int bCol = (tid & 31) * 4;

    for (int k0 = 0; k0 < K; k0 += 8) {
        float4 av = make_float4(0.f, 0.f, 0.f, 0.f);
        int ar = rowBase + aRow;
        if (ar < M) av = *reinterpret_cast<const float4*>(A + (size_t)ar * K + k0 + aCol);
        As[aCol + 0][aRow] = av.x;
        As[aCol + 1][aRow] = av.y;
        As[aCol + 2][aRow] = av.z;
        As[aCol + 3][aRow] = av.w;
        float4 bv = *reinterpret_cast<const float4*>(B + (size_t)(k0 + bRow) * N + colBase + bCol);
        *reinterpret_cast<float4*>(&Bs[bRow][bCol]) = bv;
        __syncthreads();
#pragma unroll
        for (int kk = 0; kk < 8; kk++) {
            float ar_[8], br_[8];
#pragma unroll
            for (int i = 0; i < 8; i++) ar_[i] = As[kk][ty * 8 + i];
#pragma unroll
            for (int j = 0; j < 8; j++) br_[j] = Bs[kk][tx * 8 + j];
#pragma unroll
            for (int i = 0; i < 8; i++)
#pragma unroll
                for (int j = 0; j < 8; j++) acc[i][j] += ar_[i] * br_[j];
        }
        __syncthreads();
    }
#pragma unroll
    for (int i = 0; i < 8; i++) {
        int row = rowBase + ty * 8 + i;
        if (row >= M) continue;
#pragma unroll
        for (int j = 0; j < 8; j += 4) {
            int col = colBase + tx * 8 + j;
            float4 v;
            v.x = acc[i][j + 0] + bias[col + 0];
            v.y = acc[i][j + 1] + bias[col + 1];
            v.z = acc[i][j + 2] + bias[col + 2];
            v.w = acc[i][j + 3] + bias[col + 3];
            if (relu) {
                v.x = fmaxf(v.x, 0.f); v.y = fmaxf(v.y, 0.f);
                v.z = fmaxf(v.z, 0.f); v.w = fmaxf(v.w, 0.f);
            }
            *reinterpret_cast<float4*>(C + (size_t)row * N + col) = v;
        }
    }
}

// ---------------- pooling (mean of FANIN=4), writes into Tcat slice 0 ----------------
template <int CIN, int KCDST>
__global__ void k_pool(const float* __restrict__ h, const int* __restrict__ cols,
                       float* __restrict__ dst, int n_out) {
    int warp = (blockIdx.x * blockDim.x + threadIdx.x) >> 5;
    if (warp >= n_out) return;
    int lane = threadIdx.x & 31;
    int c0 = cols[4 * warp + 0], c1 = cols[4 * warp + 1];
    int c2 = cols[4 * warp + 2], c3 = cols[4 * warp + 3];
#pragma unroll
    for (int i = lane; i < CIN; i += 32) {
        float v = 0.25f * (h[(size_t)c0 * CIN + i] + h[(size_t)c1 * CIN + i] +
                           h[(size_t)c2 * CIN + i] + h[(size_t)c3 * CIN + i]);
        dst[(size_t)warp * KCDST + i] = v;
    }
}

// ---------------- final linear ----------------
__global__ void k_lin_init(const float* __restrict__ lb, float* __restrict__ out) {
    if (threadIdx.x < 10) out[threadIdx.x] = lb[threadIdx.x];
}

__global__ void k_lin_reduce(const float* __restrict__ h, const float* __restrict__ lw,
                             float* __restrict__ out, int len) {
    const int CH = 4096;
    __shared__ float sh[CH];
    __shared__ float red[8];
    int base = blockIdx.x * CH;
    int rem = len - base;
    if (rem > CH) rem = CH;
    for (int i = threadIdx.x; i < CH; i += 256) sh[i] = (i < rem) ? h[base + i] : 0.f;
    __syncthreads();
    for (int c = 0; c < 10; c++) {
        const float* w = lw + (size_t)c * len + base;
        float s = 0.f;
        for (int i = threadIdx.x * 4; i < rem; i += 1024) {
            float4 wv = *reinterpret_cast<const float4*>(w + i);
            s += wv.x * sh[i] + wv.y * sh[i + 1] + wv.z * sh[i + 2] + wv.w * sh[i + 3];
        }
#pragma unroll
        for (int o = 16; o; o >>= 1) s += __shfl_xor_sync(0xffffffffu, s, o);
        if ((threadIdx.x & 31) == 0) red[threadIdx.x >> 5] = s;
        __syncthreads();
        if (threadIdx.x < 8) {
            float v = red[threadIdx.x];
#pragma unroll
            for (int o = 4; o; o >>= 1) v += __shfl_xor_sync(0xffu, v, o);
            if (threadIdx.x == 0) atomicAdd(&out[c], v);
        }
        __syncthreads();
    }
}

// ---------------- host side ----------------
static void build_graph(const int* ei, int E, int n,
                        float2* csr, int* deg, float* dinv, int* rstart, int* cursor, int* bsum) {
    k_zero_i<<<cdiv(n, 256), 256>>>(deg, n);
    k_hist<<<cdiv(E, 256), 256>>>(ei, E, deg);
    k_dinv<<<cdiv(n, 256), 256>>>(deg, dinv, n);
    int nb = cdiv(n, 4096);
    k_scan_reduce<<<nb, 1024>>>(deg, n, bsum);
    k_scan_bsum<<<1, 32>>>(bsum, nb);
    k_scan_write<<<nb, 1024>>>(deg, n, bsum, rstart, cursor);
    k_fill<<<cdiv(E, 256), 256>>>(ei, E, dinv, cursor, csr);
}

extern "C" void kernel_launch(void* const* d_in, const int* in_sizes, int n_in,
                              void* d_out, int out_size) {
    const float* x   = (const float*)d_in[0];
    const int*   ei0 = (const int*)d_in[1];
    const int*   ei1 = (const int*)d_in[2];
    const int*   ei2 = (const int*)d_in[3];
    const int*   pc0 = (const int*)d_in[4];
    const int*   pc1 = (const int*)d_in[5];
    const float* w0  = (const float*)d_in[6];
    const float* b0  = (const float*)d_in[7];
    const float* w1  = (const float*)d_in[8];
    const float* b1  = (const float*)d_in[9];
    const float* w2  = (const float*)d_in[10];
    const float* b2  = (const float*)d_in[11];
    const float* lw  = (const float*)d_in[12];
    const float* lb  = (const float*)d_in[13];
    float* out = (float*)d_out;

    int *deg, *rstart, *cursor, *bsum;
    float *dinv, *T0, *h0, *T1, *h1, *T2, *h2;
    float2* csr;
    cudaGetSymbolAddress((void**)&deg, g_deg);
    cudaGetSymbolAddress((void**)&dinv, g_dinv);
    cudaGetSymbolAddress((void**)&rstart, g_rstart);
    cudaGetSymbolAddress((void**)&cursor, g_cursor);
    cudaGetSymbolAddress((void**)&bsum, g_bsum);
    cudaGetSymbolAddress((void**)&csr, g_csr);
    cudaGetSymbolAddress((void**)&T0, g_T0);
    cudaGetSymbolAddress((void**)&h0, g_h0);
    cudaGetSymbolAddress((void**)&T1, g_T1);
    cudaGetSymbolAddress((void**)&h1, g_h1);
    cudaGetSymbolAddress((void**)&T2, g_T2);
    cudaGetSymbolAddress((void**)&h2, g_h2);

    // ======== LEVEL 0 (n=200000, cin=3 padded to 4, cout=64) ========
    build_graph(ei0, E0, N0, csr, deg, dinv, rstart, cursor, bsum);
    k_pad_x<<<cdiv(N0, 256), 256>>>(x, T0, N0);
    {
        int blocks = cdiv(N0, 8);  // 8 warps per block
        k_prop_w4<false><<<blocks, 256>>>(csr, rstart, deg, T0, 0, 4, 0, N0);
        k_prop_w4<true><<<blocks, 256>>>(csr, rstart, deg, T0, 4, 8, 0, N0);
        k_prop_w4<true><<<blocks, 256>>>(csr, rstart, deg, T0, 8, 12, 4, N0);
        k_prop_w4<true><<<blocks, 256>>>(csr, rstart, deg, T0, 12, 16, 8, N0);
        k_prop_w4<true><<<blocks, 256>>>(csr, rstart, deg, T0, 16, 20, 12, N0);
    }
    k_gemm0<<<cdiv(N0, 16), 256>>>(T0, w0, b0, h0, N0);
    k_pool<64, KC1><<<cdiv(N1, 8), 256>>>(h0, pc0, T1, N1);

    // ======== LEVEL 1 (n=50000, cin=64, cout=128) ========
    build_graph(ei1, E1, N1, csr, deg, dinv, rstart, cursor, bsum);
    {
        int blocks = cdiv(N1, 8);
        k_prop_wide<64, KC1, false><<<blocks, 256>>>(csr, rstart, deg, T1, 0, 64, 0, N1);
        k_prop_wide<64, KC1, true><<<blocks, 256>>>(csr, rstart, deg, T1, 64, 128, 0, N1);
        k_prop_wide<64, KC1, true><<<blocks, 256>>>(csr, rstart, deg, T1, 128, 192, 64, N1);
        k_prop_wide<64, KC1, true><<<blocks, 256>>>(csr, rstart, deg, T1, 192, 256, 128, N1);
        k_prop_wide<64, KC1, true><<<blocks, 256>>>(csr, rstart, deg, T1, 256, 320, 192, N1);
    }
    {
        dim3 grid(128 / 128, cdiv(N1, 128));  // (1, 391)
        k_sgemm<<<grid, 256>>>(T1, w1, h1, N1, 128, KC1, b1, 1);
    }
    k_pool<128, KC2><<<cdiv(N2, 8), 256>>>(h1, pc1, T2, N2);

    // ======== LEVEL 2 (n=12500, cin=128, cout=256) ========
    build_graph(ei2, E2, N2, csr, deg, dinv, rstart, cursor, bsum);
    {
        int blocks = cdiv(N2, 8);
        k_prop_wide<128, KC2, false><<<blocks, 256>>>(csr, rstart, deg, T2, 0, 128, 0, N2);
        k_prop_wide<128, KC2, true><<<blocks, 256>>>(csr, rstart, deg, T2, 128, 256, 0, N2);
        k_prop_wide<128, KC2, true><<<blocks, 256>>>(csr, rstart, deg, T2, 256, 384, 128, N2);
        k_prop_wide<128, KC2, true><<<blocks, 256>>>(csr, rstart, deg, T2, 384, 512, 256, N2);
        k_prop_wide<128, KC2, true><<<blocks, 256>>>(csr, rstart, deg, T2, 512, 640, 384, N2);
    }
    {
        dim3 grid(256 / 128, cdiv(N2, 128));  // (2, 98)
        k_sgemm<<<grid, 256>>>(T2, w2, h2, N2, 256, KC2, b2, 0);
    }

    // ======== final linear ========
    k_lin_init<<<1, 32>>>(lb, out);
    k_lin_reduce<<<cdiv(LINLEN, 4096), 256>>>(h2, lw, out, LINLEN);
}

// round 7
// speedup vs baseline: 1.1696x; 1.1696x over previous
#include <cuda_runtime.h>
#include <cuda_bf16.h>
#include <cstdint>

// ---------------- problem constants ----------------
#define N0 200000
#define N1 50000
#define N2 12500
#define E0 6400000
#define E1 1600000
#define E2 400000
#define KC0 24      // 6 cheb orders * 4 (padded cin=3 -> 4)
#define KC1 384     // 6 * 64
#define KC2 768     // 6 * 128
#define LINLEN 3200000  // 12500 * 256

// ---------------- static scratch (no allocation allowed) ----------------
__device__ int    g_deg[N0];
__device__ float  g_dinv[N0];
__device__ int    g_rstart[N0];
__device__ int    g_cursor[N0];
__device__ int    g_bsum[256];
__device__ float2 g_csr[E0];                       // (col-as-bits, norm) reused per level
__device__ float  g_T0[(size_t)N0 * KC0];
__device__ float  g_h0[(size_t)N0 * 64];
__device__ float  g_T1[(size_t)N1 * KC1];
__device__ float  g_h1[(size_t)N1 * 128];
__device__ float  g_T2[(size_t)N2 * KC2];
__device__ float  g_h2[(size_t)N2 * 256];
// bf16 hi/lo weight matrices, layout [N, K] (row n = output channel)
__device__ __nv_bfloat16 g_b1h[128 * KC1];
__device__ __nv_bfloat16 g_b1l[128 * KC1];
__device__ __nv_bfloat16 g_b2h[256 * KC2];
__device__ __nv_bfloat16 g_b2l[256 * KC2];
// bf16 hi/lo activation matrices (A operands)
__device__ __nv_bfloat16 g_a1h[(size_t)N1 * KC1];
__device__ __nv_bfloat16 g_a1l[(size_t)N1 * KC1];
__device__ __nv_bfloat16 g_a2h[(size_t)N2 * KC2];
__device__ __nv_bfloat16 g_a2l[(size_t)N2 * KC2];

static inline int cdiv(int a, int b) { return (a + b - 1) / b; }

// ---------------- graph build ----------------
__global__ void k_zero_i(int* p, int n) {
    int i = blockIdx.x * blockDim.x + threadIdx.x;
    if (i < n) p[i] = 0;
}

__global__ void k_hist(const int* __restrict__ ei, int E, int* __restrict__ deg) {
    int e = blockIdx.x * blockDim.x + threadIdx.x;
    if (e < E) {
        int r = ei[e], c = ei[E + e];
        if (r != c) atomicAdd(&deg[r], 1);
    }
}

__global__ void k_dinv(const int* __restrict__ deg, float* __restrict__ dinv, int n) {
    int i = blockIdx.x * blockDim.x + threadIdx.x;
    if (i < n) {
        int d = deg[i];
        dinv[i] = d > 0 ? rsqrtf((float)d) : 0.f;
    }
}

// scan: 4096 elems per block
__global__ void k_scan_reduce(const int* __restrict__ deg, int n, int* __restrict__ bsum) {
    __shared__ int sm[1024];
    int base = blockIdx.x * 4096;
    int s = 0;
    for (int i = threadIdx.x; i < 4096; i += 1024) {
        int id = base + i;
        if (id < n) s += deg[id];
    }
    sm[threadIdx.x] = s;
    __syncthreads();
    for (int o = 512; o > 0; o >>= 1) {
        if (threadIdx.x < o) sm[threadIdx.x] += sm[threadIdx.x + o];
        __syncthreads();
    }
    if (threadIdx.x == 0) bsum[blockIdx.x] = sm[0];
}

__global__ void k_scan_bsum(int* bsum, int nb) {
    if (threadIdx.x == 0) {
        int acc = 0;
        for (int i = 0; i < nb; i++) { int v = bsum[i]; bsum[i] = acc; acc += v; }
    }
}

__global__ void k_scan_write(const int* __restrict__ deg, int n, const int* __restrict__ bsum,
                             int* __restrict__ rstart, int* __restrict__ cursor) {
    __shared__ int wsum[32];
    int lane = threadIdx.x & 31, wid = threadIdx.x >> 5;
    int base = blockIdx.x * 4096;
    int idx0 = base + threadIdx.x * 4;
    int v[4]; int s = 0;
#pragma unroll
    for (int j = 0; j < 4; j++) {
        int id = idx0 + j;
        v[j] = (id < n) ? deg[id] : 0;
        s += v[j];
    }
    int x = s;
#pragma unroll
    for (int o = 1; o < 32; o <<= 1) {
        int y = __shfl_up_sync(0xffffffffu, x, o);
        if (lane >= o) x += y;
    }
    if (lane == 31) wsum[wid] = x;
    __syncthreads();
    if (wid == 0) {
        int w = wsum[lane];
#pragma unroll
        for (int o = 1; o < 32; o <<= 1) {
            int y = __shfl_up_sync(0xffffffffu, w, o);
            if (lane >= o) w += y;
        }
        wsum[lane] = w;
    }
    __syncthreads();
    int run = bsum[blockIdx.x] + (wid ? wsum[wid - 1] : 0) + (x - s);
#pragma unroll
    for (int j = 0; j < 4; j++) {
        int id = idx0 + j;
        if (id < n) { rstart[id] = run; cursor[id] = run; }
        run += v[j];
    }
}

__global__ void k_fill(const int* __restrict__ ei, int E, const float* __restrict__ dinv,
                       int* __restrict__ cursor, float2* __restrict__ csr) {
    int e = blockIdx.x * blockDim.x + threadIdx.x;
    if (e < E) {
        int r = ei[e], c = ei[E + e];
        if (r != c) {
            int p = atomicAdd(&cursor[r], 1);
            csr[p] = make_float2(__int_as_float(c), -dinv[r] * dinv[c]);
        }
    }
}

// ---------------- level 0 ----------------
__global__ void k_pad_x(const float* __restrict__ x, float* __restrict__ T0, int n) {
    int i = blockIdx.x * blockDim.x + threadIdx.x;
    if (i < n) {
        float4 v;
        v.x = x[3 * i]; v.y = x[3 * i + 1]; v.z = x[3 * i + 2]; v.w = 0.f;
        *reinterpret_cast<float4*>(T0 + (size_t)i * KC0) = v;
    }
}

// width-4 propagation: warp per node, lanes over edges, float4 gather + warp reduce
template <bool HASPP>
__global__ void k_prop_w4(const float2* __restrict__ csr, const int* __restrict__ rstart,
                          const int* __restrict__ deg, float* __restrict__ T,
                          int off_src, int off_dst, int off_pp, int n) {
    int warp = (blockIdx.x * blockDim.x + threadIdx.x) >> 5;
    if (warp >= n) return;
    int lane = threadIdx.x & 31;
    int s = rstart[warp], d = deg[warp];
    const float* src = T + off_src;
    float ax = 0.f, ay = 0.f, az = 0.f, aw = 0.f;
    for (int e = s + lane; e < s + d; e += 32) {
        float2 cw = csr[e];
        int c = __float_as_int(cw.x);
        float w = cw.y;
        float4 h = *reinterpret_cast<const float4*>(src + (size_t)c * KC0);
        ax += w * h.x; ay += w * h.y; az += w * h.z; aw += w * h.w;
    }
#pragma unroll
    for (int o = 16; o; o >>= 1) {
        ax += __shfl_xor_sync(0xffffffffu, ax, o);
        ay += __shfl_xor_sync(0xffffffffu, ay, o);
        az += __shfl_xor_sync(0xffffffffu, az, o);
        aw += __shfl_xor_sync(0xffffffffu, aw, o);
    }
    if (lane == 0) {
        float4 r = make_float4(ax, ay, az, aw);
        if (HASPP) {
            float4 p = *reinterpret_cast<const float4*>(T + off_pp + (size_t)warp * KC0);
            r.x = 2.f * ax - p.x; r.y = 2.f * ay - p.y; r.z = 2.f * az - p.z; r.w = 2.f * aw - p.w;
        }
        *reinterpret_cast<float4*>(T + off_dst + (size_t)warp * KC0) = r;
    }
}

// wide propagation: warp per node, lanes over channels, broadcast edge loads
template <int CIN, int KC, bool HASPP>
__global__ void k_prop_wide(const float2* __restrict__ csr, const int* __restrict__ rstart,
                            const int* __restrict__ deg, float* __restrict__ T,
                            int off_src, int off_dst, int off_pp, int n) {
    int warp = (blockIdx.x * blockDim.x + threadIdx.x) >> 5;
    if (warp >= n) return;
    int lane = threadIdx.x & 31;
    int s = rstart[warp], d = deg[warp];
    constexpr int R = CIN / 32;
    float acc[R];
#pragma unroll
    for (int i = 0; i < R; i++) acc[i] = 0.f;
    const float* src = T + off_src;
    int e = s, end = s + d;
    for (; e + 1 < end; e += 2) {
        float2 cw0 = __ldg(&csr[e]);
        float2 cw1 = __ldg(&csr[e + 1]);
        int c0 = __float_as_int(cw0.x); float w0 = cw0.y;
        int c1 = __float_as_int(cw1.x); float w1 = cw1.y;
        const float* h0 = src + (size_t)c0 * KC + lane;
        const float* h1 = src + (size_t)c1 * KC + lane;
#pragma unroll
        for (int i = 0; i < R; i++) acc[i] += w0 * h0[32 * i];
#pragma unroll
        for (int i = 0; i < R; i++) acc[i] += w1 * h1[32 * i];
    }
    if (e < end) {
        float2 cw = __ldg(&csr[e]);
        int c = __float_as_int(cw.x); float w = cw.y;
        const float* h = src + (size_t)c * KC + lane;
#pragma unroll
        for (int i = 0; i < R; i++) acc[i] += w * h[32 * i];
    }
    float* dst = T + off_dst + (size_t)warp * KC + lane;
    if (HASPP) {
        const float* pp = T + off_pp + (size_t)warp * KC + lane;
#pragma unroll
        for (int i = 0; i < R; i++) dst[32 * i] = 2.f * acc[i] - pp[32 * i];
    } else {
#pragma unroll
        for (int i = 0; i < R; i++) dst[32 * i] = acc[i];
    }
}

// ---------------- level-0 GEMM: [n,24(pad)] x w0[6,3,64] + relu ----------------
__global__ void k_gemm0(const float* __restrict__ T0, const float* __restrict__ w,
                        const float* __restrict__ b, float* __restrict__ h0, int n) {
    __shared__ float Ws[1152];   // 6*3*64
    __shared__ float As[16][24];
    int tid = threadIdx.x;
    for (int i = tid; i < 1152; i += 256) Ws[i] = w[i];
    int node0 = blockIdx.x * 16;
    for (int i = tid; i < 384; i += 256) {
        int nn = i / 24, j = i % 24;
        int nd = node0 + nn;
        As[nn][j] = (nd < n) ? T0[(size_t)nd * KC0 + j] : 0.f;
    }
    __syncthreads();
    int co = tid & 63, g = tid >> 6;  // g in 0..3
#pragma unroll
    for (int sblk = 0; sblk < 4; sblk++) {
        int nn = g * 4 + sblk;
        int node = node0 + nn;
        if (node < n) {
            float s = b[co];
#pragma unroll
            for (int k = 0; k < 6; k++)
#pragma unroll
                for (int j = 0; j < 3; j++)
                    s += As[nn][k * 4 + j] * Ws[(k * 3 + j) * 64 + co];
            h0[(size_t)node * 64 + co] = fmaxf(s, 0.f);
        }
    }
}

// =====================================================================
// bf16x3 emulated-fp32 GEMM via mma.sync (sm_80 baseline ISA — no tcgen05)
// =====================================================================
__device__ __forceinline__ uint32_t s2u(const void* p) {
    uint32_t a;
    asm("{ .reg .u64 t; cvta.to.shared.u64 t, %1; cvt.u32.u64 %0, t; }" : "=r"(a) : "l"(p));
    return a;
}

__device__ __forceinline__ void cp16(uint32_t d, const void* s) {
    asm volatile("cp.async.cg.shared.global [%0], [%1], 16;" :: "r"(d), "l"(s));
}

__device__ __forceinline__ void ldm_x4(uint32_t* r, uint32_t addr) {
    asm volatile("ldmatrix.sync.aligned.m8n8.x4.shared.b16 {%0,%1,%2,%3}, [%4];"
                 : "=r"(r[0]), "=r"(r[1]), "=r"(r[2]), "=r"(r[3]) : "r"(addr));
}

__device__ __forceinline__ void ldm_x2(uint32_t* r, uint32_t addr) {
    asm volatile("ldmatrix.sync.aligned.m8n8.x2.shared.b16 {%0,%1}, [%2];"
                 : "=r"(r[0]), "=r"(r[1]) : "r"(addr));
}

__device__ __forceinline__ void mma_bf16(float* c, const uint32_t* a, const uint32_t* b) {
    asm volatile(
        "mma.sync.aligned.m16n8k16.row.col.f32.bf16.bf16.f32 "
        "{%0,%1,%2,%3}, {%4,%5,%6,%7}, {%8,%9}, {%0,%1,%2,%3};"
        : "+f"(c[0]), "+f"(c[1]), "+f"(c[2]), "+f"(c[3])
        : "r"(a[0]), "r"(a[1]), "r"(a[2]), "r"(a[3]), "r"(b[0]), "r"(b[1]));
}

// prep: W [Kt, N] fp32 row-major -> Bhi/Blo [N, Kt] bf16 (hi + residual-lo split)
__global__ void k_prep_w(const float* __restrict__ w, __nv_bfloat16* __restrict__ bhi,
                         __nv_bfloat16* __restrict__ blo, int Kt, int N) {
    int idx = blockIdx.x * blockDim.x + threadIdx.x;
    if (idx < Kt * N) {
        int k = idx / N, n = idx - k * N;
        float v = w[idx];
        __nv_bfloat16 h = __float2bfloat16(v);
        __nv_bfloat16 l = __float2bfloat16(v - __bfloat162float(h));
        bhi[(size_t)n * Kt + k] = h;
        blo[(size_t)n * Kt + k] = l;
    }
}

// elementwise fp32 -> bf16 hi/lo (A operand), vectorized x4
__global__ void k_cvt_hilo(const float* __restrict__ a, __nv_bfloat16* __restrict__ h,
                           __nv_bfloat16* __restrict__ l, int n4) {
    int i = blockIdx.x * blockDim.x + threadIdx.x;
    if (i < n4) {
        float4 v = *reinterpret_cast<const float4*>(a + (size_t)i * 4);
        __nv_bfloat162 h0, h1, l0, l1;
        h0.x = __float2bfloat16(v.x); h0.y = __float2bfloat16(v.y);
        h1.x = __float2bfloat16(v.z); h1.y = __float2bfloat16(v.w);
        l0.x = __float2bfloat16(v.x - __bfloat162float(h0.x));
        l0.y = __float2bfloat16(v.y - __bfloat162float(h0.y));
        l1.x = __float2bfloat16(v.z - __bfloat162float(h1.x));
        l1.y = __float2bfloat16(v.w - __bfloat162float(h1.y));
        reinterpret_cast<__nv_bfloat162*>(h)[2 * (size_t)i + 0] = h0;
        reinterpret_cast<__nv_bfloat162*>(h)[2 * (size_t)i + 1] = h1;
        reinterpret_cast<__nv_bfloat162*>(l)[2 * (size_t)i + 0] = l0;
        reinterpret_cast<__nv_bfloat162*>(l)[2 * (size_t)i + 1] = l1;
    }
}

// C[m, colBase+n] = sum_k A[m,k]*W[k,colBase+n] + bias, optional relu.
// Ah/Al bf16 [M, KTOT]; Bh/Bl bf16 [Ntot, KTOT]. Block 128x128, 8 warps (2x4),
// warp tile 64x32 of m16n8k16 mmas, 3 passes (hi*hi, hi*lo, lo*hi).
// Smem: 2 stages x {Ah,Al,Bh,Bl} each 128 rows x 80B (32 bf16 + 8 pad).
template <int KTOT>
__global__ __launch_bounds__(256) void k_mma_gemm(
    const __nv_bfloat16* __restrict__ Ah, const __nv_bfloat16* __restrict__ Al,
    const __nv_bfloat16* __restrict__ Bh, const __nv_bfloat16* __restrict__ Bl,
    float* __restrict__ C, const float* __restrict__ bias, int M, int ldc, int relu)
{
    extern __shared__ char smem[];
    constexpr int NCH = KTOT / 32;
    constexpr int STAGE = 40960;   // 4 matrices * 128 * 80
    const int tid = threadIdx.x, lane = tid & 31, wid = tid >> 5;
    const int wr = wid >> 2, wc = wid & 3;
    const int m0 = blockIdx.y * 128, colBase = blockIdx.x * 128;
    const uint32_t sb = s2u(smem);

    float acc[4][4][4];
#pragma unroll
    for (int i = 0; i < 4; i++)
#pragma unroll
        for (int j = 0; j < 4; j++)
#pragma unroll
            for (int q = 0; q < 4; q++) acc[i][j][q] = 0.f;

    // ---- async copy of one K-chunk into stage (c&1) ----
    auto issue = [&](int c) {
        uint32_t st = sb + (uint32_t)(c & 1) * STAGE;
        int k0 = c * 32;
#pragma unroll
        for (int mat = 0; mat < 2; mat++) {
            const __nv_bfloat16* src = mat ? Al : Ah;
            uint32_t db = st + mat * 10240;
#pragma unroll
            for (int j = 0; j < 2; j++) {
                int id = tid + j * 256;
                int row = id >> 2, seg = id & 3;
                int rg = m0 + row; rg = rg < M ? rg : M - 1;
                cp16(db + row * 80 + seg * 16, src + (size_t)rg * KTOT + k0 + seg * 8);
            }
        }
#pragma unroll
        for (int mat = 0; mat < 2; mat++) {
            const __nv_bfloat16* src = mat ? Bl : Bh;
            uint32_t db = st + 20480 + mat * 10240;
#pragma unroll
            for (int j = 0; j < 2; j++) {
                int id = tid + j * 256;
                int row = id >> 2, seg = id & 3;
                cp16(db + row * 80 + seg * 16, src + (size_t)(colBase + row) * KTOT + k0 + seg * 8);
            }
        }
    };

    issue(0);
    asm volatile("cp.async.commit_group;" ::: "memory");

    for (int c = 0; c < NCH; c++) {
        if (c + 1 < NCH) issue(c + 1);
        asm volatile("cp.async.commit_group;" ::: "memory");
        asm volatile("cp.async.wait_group 1;" ::: "memory");
        __syncthreads();

        uint32_t st = sb + (uint32_t)(c & 1) * STAGE;
#pragma unroll
        for (int ks = 0; ks < 2; ks++) {
            uint32_t ahi[4][4], alo[4][4], bhi[4][2], blo[4][2];
            int acol = (ks * 16 + (lane >> 4) * 8) * 2;
            int arow = lane & 15;
#pragma unroll
            for (int mt = 0; mt < 4; mt++) {
                uint32_t ad = st + (wr * 64 + mt * 16 + arow) * 80 + acol;
                ldm_x4(ahi[mt], ad);
                ldm_x4(alo[mt], ad + 10240);
            }
            int bcol = (ks * 16 + ((lane >> 3) & 1) * 8) * 2;
            int brow = lane & 7;
#pragma unroll
            for (int nt = 0; nt < 4; nt++) {
                uint32_t bd = st + 20480 + (wc * 32 + nt * 8 + brow) * 80 + bcol;
                ldm_x2(bhi[nt], bd);
                ldm_x2(blo[nt], bd + 10240);
            }
#pragma unroll
            for (int mt = 0; mt < 4; mt++)
#pragma unroll
                for (int nt = 0; nt < 4; nt++) {
                    mma_bf16(acc[mt][nt], ahi[mt], bhi[nt]);
                    mma_bf16(acc[mt][nt], ahi[mt], blo[nt]);
                    mma_bf16(acc[mt][nt], alo[mt], bhi[nt]);
                }
        }
        __syncthreads();
    }

    // ---- epilogue ----
#pragma unroll
    for (int mt = 0; mt < 4; mt++) {
        int r0 = m0 + wr * 64 + mt * 16 + (lane >> 2);
#pragma unroll
        for (int nt = 0; nt < 4; nt++) {
            int col = colBase + wc * 32 + nt * 8 + (lane & 3) * 2;
            float bx = bias[col], by = bias[col + 1];
            float2 v0 = make_float2(acc[mt][nt][0] + bx, acc[mt][nt][1] + by);
            float2 v1 = make_float2(acc[mt][nt][2] + bx, acc[mt][nt][3] + by);
            if (relu) {
                v0.x = fmaxf(v0.x, 0.f); v0.y = fmaxf(v0.y, 0.f);
                v1.x = fmaxf(v1.x, 0.f); v1.y = fmaxf(v1.y, 0.f);
            }
            if (r0 < M) *reinterpret_cast<float2*>(C + (size_t)r0 * ldc + col) = v0;
            if (r0 + 8 < M) *reinterpret_cast<float2*>(C + (size_t)(r0 + 8) * ldc + col) = v1;
        }
    }
}

// ---------------- pooling (mean of FANIN=4), writes into Tcat slice 0 ----------------
template <int CIN, int KCDST>
__global__ void k_pool(const float* __restrict__ h, const int* __restrict__ cols,
                       float* __restrict__ dst, int n_out) {
    int warp = (blockIdx.x * blockDim.x + threadIdx.x) >> 5;
    if (warp >= n_out) return;
    int lane = threadIdx.x & 31;
    int c0 = cols[4 * warp + 0], c1 = cols[4 * warp + 1];
    int c2 = cols[4 * warp + 2], c3 = cols[4 * warp + 3];
#pragma unroll
    for (int i = lane; i < CIN; i += 32) {
        float v = 0.25f * (h[(size_t)c0 * CIN + i] + h[(size_t)c1 * CIN + i] +
                           h[(size_t)c2 * CIN + i] + h[(size_t)c3 * CIN + i]);
        dst[(size_t)warp * KCDST + i] = v;
    }
}

// ---------------- final linear ----------------
__global__ void k_lin_init(const float* __restrict__ lb, float* __restrict__ out) {
    if (threadIdx.x < 10) out[threadIdx.x] = lb[threadIdx.x];
}

__global__ void k_lin_reduce(const float* __restrict__ h, const float* __restrict__ lw,
                             float* __restrict__ out, int len) {
    const int CH = 4096;
    __shared__ float sh[CH];
    __shared__ float red[8];
    int base = blockIdx.x * CH;
    int rem = len - base;
    if (rem > CH) rem = CH;
    for (int i = threadIdx.x; i < CH; i += 256) sh[i] = (i < rem) ? h[base + i] : 0.f;
    __syncthreads();
    for (int c = 0; c < 10; c++) {
        const float* w = lw + (size_t)c * len + base;
        float s = 0.f;
        for (int i = threadIdx.x * 4; i < rem; i += 1024) {
            float4 wv = *reinterpret_cast<const float4*>(w + i);
            s += wv.x * sh[i] + wv.y * sh[i + 1] + wv.z * sh[i + 2] + wv.w * sh[i + 3];
        }
#pragma unroll
        for (int o = 16; o; o >>= 1) s += __shfl_xor_sync(0xffffffffu, s, o);
        if ((threadIdx.x & 31) == 0) red[threadIdx.x >> 5] = s;
        __syncthreads();
        if (threadIdx.x < 8) {
            float v = red[threadIdx.x];
#pragma unroll
            for (int o = 4; o; o >>= 1) v += __shfl_xor_sync(0xffu, v, o);
            if (threadIdx.x == 0) atomicAdd(&out[c], v);
        }
        __syncthreads();
    }
}

// ---------------- host side ----------------
static void build_graph(const int* ei, int E, int n,
                        float2* csr, int* deg, float* dinv, int* rstart, int* cursor, int* bsum) {
    k_zero_i<<<cdiv(n, 256), 256>>>(deg, n);
    k_hist<<<cdiv(E, 256), 256>>>(ei, E, deg);
    k_dinv<<<cdiv(n, 256), 256>>>(deg, dinv, n);
    int nb = cdiv(n, 4096);
    k_scan_reduce<<<nb, 1024>>>(deg, n, bsum);
    k_scan_bsum<<<1, 32>>>(bsum, nb);
    k_scan_write<<<nb, 1024>>>(deg, n, bsum, rstart, cursor);
    k_fill<<<cdiv(E, 256), 256>>>(ei, E, dinv, cursor, csr);
}

extern "C" void kernel_launch(void* const* d_in, const int* in_sizes, int n_in,
                              void* d_out, int out_size) {
    const float* x   = (const float*)d_in[0];
    const int*   ei0 = (const int*)d_in[1];
    const int*   ei1 = (const int*)d_in[2];
    const int*   ei2 = (const int*)d_in[3];
    const int*   pc0 = (const int*)d_in[4];
    const int*   pc1 = (const int*)d_in[5];
    const float* w0  = (const float*)d_in[6];
    const float* b0  = (const float*)d_in[7];
    const float* w1  = (const float*)d_in[8];
    const float* b1  = (const float*)d_in[9];
    const float* w2  = (const float*)d_in[10];
    const float* b2  = (const float*)d_in[11];
    const float* lw  = (const float*)d_in[12];
    const float* lb  = (const float*)d_in[13];
    float* out = (float*)d_out;

    int *deg, *rstart, *cursor, *bsum;
    float *dinv, *T0, *h0, *T1, *h1, *T2, *h2;
    float2* csr;
    __nv_bfloat16 *b1h, *b1l, *b2h, *b2l, *a1h, *a1l, *a2h, *a2l;
    cudaGetSymbolAddress((void**)&deg, g_deg);
    cudaGetSymbolAddress((void**)&dinv, g_dinv);
    cudaGetSymbolAddress((void**)&rstart, g_rstart);
    cudaGetSymbolAddress((void**)&cursor, g_cursor);
    cudaGetSymbolAddress((void**)&bsum, g_bsum);
    cudaGetSymbolAddress((void**)&csr, g_csr);
    cudaGetSymbolAddress((void**)&T0, g_T0);
    cudaGetSymbolAddress((void**)&h0, g_h0);
    cudaGetSymbolAddress((void**)&T1, g_T1);
    cudaGetSymbolAddress((void**)&h1, g_h1);
    cudaGetSymbolAddress((void**)&T2, g_T2);
    cudaGetSymbolAddress((void**)&h2, g_h2);
    cudaGetSymbolAddress((void**)&b1h, g_b1h);
    cudaGetSymbolAddress((void**)&b1l, g_b1l);
    cudaGetSymbolAddress((void**)&b2h, g_b2h);
    cudaGetSymbolAddress((void**)&b2l, g_b2l);
    cudaGetSymbolAddress((void**)&a1h, g_a1h);
    cudaGetSymbolAddress((void**)&a1l, g_a1l);
    cudaGetSymbolAddress((void**)&a2h, g_a2h);
    cudaGetSymbolAddress((void**)&a2l, g_a2l);

    const int GEMM_SMEM = 2 * 40960;   // 81920 bytes
    cudaFuncSetAttribute(k_mma_gemm<KC1>, cudaFuncAttributeMaxDynamicSharedMemorySize, GEMM_SMEM);
    cudaFuncSetAttribute(k_mma_gemm<KC2>, cudaFuncAttributeMaxDynamicSharedMemorySize, GEMM_SMEM);

    // weight prep (cheap, done up-front)
    k_prep_w<<<cdiv(KC1 * 128, 256), 256>>>(w1, b1h, b1l, KC1, 128);
    k_prep_w<<<cdiv(KC2 * 256, 256), 256>>>(w2, b2h, b2l, KC2, 256);

    // ======== LEVEL 0 (n=200000, cin=3 padded to 4, cout=64) ========
    build_graph(ei0, E0, N0, csr, deg, dinv, rstart, cursor, bsum);
    k_pad_x<<<cdiv(N0, 256), 256>>>(x, T0, N0);
    {
        int blocks = cdiv(N0, 8);  // 8 warps per block
        k_prop_w4<false><<<blocks, 256>>>(csr, rstart, deg, T0, 0, 4, 0, N0);
        k_prop_w4<true><<<blocks, 256>>>(csr, rstart, deg, T0, 4, 8, 0, N0);
        k_prop_w4<true><<<blocks, 256>>>(csr, rstart, deg, T0, 8, 12, 4, N0);
        k_prop_w4<true><<<blocks, 256>>>(csr, rstart, deg, T0, 12, 16, 8, N0);
        k_prop_w4<true><<<blocks, 256>>>(csr, rstart, deg, T0, 16, 20, 12, N0);
    }
    k_gemm0<<<cdiv(N0, 16), 256>>>(T0, w0, b0, h0, N0);
    k_pool<64, KC1><<<cdiv(N1, 8), 256>>>(h0, pc0, T1, N1);

    // ======== LEVEL 1 (n=50000, cin=64, cout=128) ========
    build_graph(ei1, E1, N1, csr, deg, dinv, rstart, cursor, bsum);
    {
        int blocks = cdiv(N1, 8);
        k_prop_wide<64, KC1, false><<<blocks, 256>>>(csr, rstart, deg, T1, 0, 64, 0, N1);
        k_prop_wide<64, KC1, true><<<blocks, 256>>>(csr, rstart, deg, T1, 64, 128, 0, N1);
        k_prop_wide<64, KC1, true><<<blocks, 256>>>(csr, rstart, deg, T1, 128, 192, 64, N1);
        k_prop_wide<64, KC1, true><<<blocks, 256>>>(csr, rstart, deg, T1, 192, 256, 128, N1);
        k_prop_wide<64, KC1, true><<<blocks, 256>>>(csr, rstart, deg, T1, 256, 320, 192, N1);
    }
    k_cvt_hilo<<<cdiv(N1 * KC1 / 4, 256), 256>>>(T1, a1h, a1l, N1 * KC1 / 4);
    k_mma_gemm<KC1><<<dim3(1, cdiv(N1, 128)), 256, GEMM_SMEM>>>(a1h, a1l, b1h, b1l, h1, b1, N1, 128, 1);
    k_pool<128, KC2><<<cdiv(N2, 8), 256>>>(h1, pc1, T2, N2);

    // ======== LEVEL 2 (n=12500, cin=128, cout=256) ========
    build_graph(ei2, E2, N2, csr, deg, dinv, rstart, cursor, bsum);
    {
        int blocks = cdiv(N2, 8);
        k_prop_wide<128, KC2, false><<<blocks, 256>>>(csr, rstart, deg, T2, 0, 128, 0, N2);
        k_prop_wide<128, KC2, true><<<blocks, 256>>>(csr, rstart, deg, T2, 128, 256, 0, N2);
        k_prop_wide<128, KC2, true><<<blocks, 256>>>(csr, rstart, deg, T2, 256, 384, 128, N2);
        k_prop_wide<128, KC2, true><<<blocks, 256>>>(csr, rstart, deg, T2, 384, 512, 256, N2);
        k_prop_wide<128, KC2, true><<<blocks, 256>>>(csr, rstart, deg, T2, 512, 640, 384, N2);
    }
    k_cvt_hilo<<<cdiv(N2 * KC2 / 4, 256), 256>>>(T2, a2h, a2l, N2 * KC2 / 4);
    k_mma_gemm<KC2><<<dim3(2, cdiv(N2, 128)), 256, GEMM_SMEM>>>(a2h, a2l, b2h, b2l, h2, b2, N2, 256, 0);

    // ======== final linear ========
    k_lin_init<<<1, 32>>>(lb, out);
    k_lin_reduce<<<cdiv(LINLEN, 4096), 256>>>(h2, lw, out, LINLEN);
}